// round 17
// baseline (speedup 1.0000x reference)
#include <cuda_runtime.h>
#include <cuda_bf16.h>

#define EE 1024
#define BB 256
#define DIN 784
#define DH 400
#define DOUT 10
#define PF 4
#define CEVT 64                 // events per chunk
#define NCH (EE / CEVT)         // 16 chunks
#define CAPC 1024               // stream entries per chunk buffer (avg ~450)
#define NT 448                  // 13 producer warps + 1 chain warp
#define OVF 0xFFFFFFFFu

#define BAR_SYNC(id, n)   asm volatile("bar.sync %0, %1;"   :: "r"(id), "r"(n) : "memory")
#define BAR_ARRIVE(id, n) asm volatile("bar.arrive %0, %1;" :: "r"(id), "r"(n) : "memory")

// Static device scratch (no cudaMalloc allowed)
__device__ float g_W1T[DIN * DH + 32];      // transposed W1 (+pad)
__device__ float g_W2r[(DH + 1) * DOUT];    // [401][10], row 400 = 0

__global__ void prep_kernel(const float* __restrict__ W1,
                            const float* __restrict__ W2,
                            const float* __restrict__ b2) {
    int idx = blockIdx.x * blockDim.x + threadIdx.x;
    if (idx < DIN * DH) {
        int p = idx / DH;
        int j = idx - p * DH;
        g_W1T[idx] = W1[j * DIN + p];
    } else if (idx < DIN * DH + (DH + 1) * DOUT) {
        int i = idx - DIN * DH;
        int j = i / DOUT;
        int d = i - j * DOUT;
        g_W2r[i] = (j < DH)
            ? __fadd_rn(W2[d * DH + j], __fdiv_rn(b2[d], 400.0f))
            : 0.0f;
    }
}

#define SM_BYTES ((EE + PF) * 8 + EE * 4 + (DH + 1) * DOUT * 4 \
                + 2 * CEVT * 13 * 4 + 2 * CAPC * 4 + 2 * CAPC * 2 \
                + 2 * CEVT * 4 + 2 * 4 + 64)

// Fused kernel: one CTA per sample.
//  warps 0..12 : layer-1 (400 neurons) -> masks -> compact (m,j) stream in SMEM
//  warp  13    : layer-2 chain (8-cyc/entry speculative-reset recurrence)
// Barrier 1 (448): producers arrive "chunk ready", chain syncs.
// Barrier 2 (448): chain arrives "chunk consumed", producers sync (depth-2 backpressure).
// Barrier 3 (416): producer-internal (masks visible / offsets visible).
__global__ __launch_bounds__(NT, 2) void snn_fused(
    const float* __restrict__ times,
    const int*   __restrict__ pix,
    const float* __restrict__ b1,
    float*       __restrict__ out)
{
    extern __shared__ unsigned char dyn[];
    float2*         s_ev   = (float2*)dyn;                         // [EE+PF]
    float*          s_d2   = (float*)(s_ev + EE + PF);             // [EE]
    float*          s_W2p  = s_d2 + EE;                            // [401*10]
    unsigned*       s_mask = (unsigned*)(s_W2p + (DH + 1) * DOUT); // [2][CEVT][13]
    float*          s_m    = (float*)(s_mask + 2 * CEVT * 13);     // [2][CAPC]
    unsigned short* s_j    = (unsigned short*)(s_m + 2 * CAPC);    // [2][CAPC]
    unsigned*       s_off  = (unsigned*)(s_j + 2 * CAPC);          // [2][CEVT]
    unsigned*       s_T    = s_off + 2 * CEVT;                     // [2]

    const float TAUF = 0.6213349345596119f;  // float(-1/ln(0.2))
    const int b    = blockIdx.x;
    const int tid  = threadIdx.x;
    const int warp = tid >> 5;
    const int lane = tid & 31;

    // ---- prologue: event data, decays, W2 to shared ----
    for (int e = tid; e < EE; e += NT) {
        float t  = times[b * EE + e];
        float tp = (e > 0) ? times[b * EE + e - 1] : 0.0f;
        float d1 = expf(__fdiv_rn(-(t - tp), TAUF));
        float th  = __fadd_rn(t, 0.1f);
        float thp = (e > 0) ? __fadd_rn(tp, 0.1f) : 0.0f;
        s_d2[e] = expf(__fdiv_rn(-(th - thp), TAUF));
        int p = pix[b * EE + e];
        s_ev[e] = make_float2(d1, __int_as_float(p * (DH * 4)));
    }
    if (tid < PF) s_ev[EE + tid] = make_float2(1.0f, __int_as_float(0));
    for (int i = tid; i < (DH + 1) * DOUT; i += NT) s_W2p[i] = g_W2r[i];
    __syncthreads();

    if (warp < 13) {
        // =================== producers ===================
        const bool valid = (tid < DH);
        float bias1j = valid ? __fdiv_rn(b1[tid], 784.0f) : 0.0f;
        const char* w1b = (const char*)g_W1T + tid * 4;

        // speculative-reset state: u1 = pre-reset membrane, fprev = fired flag
        float u1 = 0.0f;
        bool  fprev = false;

        float wbuf[PF], dbuf[PF];
        #pragma unroll
        for (int i = 0; i < PF; ++i) {
            float2 ev = s_ev[i];
            dbuf[i] = ev.x;
            wbuf[i] = *(const float*)(w1b + __float_as_int(ev.y));
        }

        for (int k = 0; k < NCH; ++k) {
            if (k >= 2) BAR_SYNC(2, NT);     // chain done with chunk k-2
            const int buf = k & 1;
            unsigned* mk = s_mask + buf * CEVT * 13;

            // ---- layer-1 over this chunk's 64 events ----
            for (int e0 = 0; e0 < CEVT; e0 += PF) {
                #pragma unroll
                for (int u = 0; u < PF; ++u) {
                    const int e = k * CEVT + e0 + u;
                    float2 evn = s_ev[e + PF];
                    float d = dbuf[u], w = wbuf[u];
                    dbuf[u] = evn.x;
                    wbuf[u] = *(const float*)(w1b + __float_as_int(evn.y));

                    // t: value if not previously fired; alt: if fired (h1 was 0)
                    float t   = __fadd_rn(__fadd_rn(__fmul_rn(u1, d), w), bias1j);
                    float alt = __fadd_rn(w, bias1j);
                    u1 = fprev ? alt : t;
                    bool fired = valid && (u1 >= 0.5f);
                    fprev = fired;
                    unsigned m = __ballot_sync(0xffffffffu, fired);
                    if (lane == 0) mk[(e0 + u) * 13 + warp] = m;
                }
            }
            BAR_SYNC(3, 416);                // all masks of chunk k visible

            // ---- warp 0: counts + exclusive prefix + padding ----
            if (warp == 0) {
                unsigned c0 = 0, c1 = 0;
                #pragma unroll
                for (int w = 0; w < 13; ++w) {
                    c0 += __popc(mk[lane * 13 + w]);
                    c1 += __popc(mk[(lane + 32) * 13 + w]);
                }
                unsigned n0 = c0 + 1, n1 = c1 + 1;   // +1 decay entry
                unsigned s0 = n0;
                #pragma unroll
                for (int d = 1; d < 32; d <<= 1) {
                    unsigned v = __shfl_up_sync(0xffffffffu, s0, d);
                    if (lane >= d) s0 += v;
                }
                unsigned tot0 = __shfl_sync(0xffffffffu, s0, 31);
                unsigned s1 = n1;
                #pragma unroll
                for (int d = 1; d < 32; d <<= 1) {
                    unsigned v = __shfl_up_sync(0xffffffffu, s1, d);
                    if (lane >= d) s1 += v;
                }
                s1 += tot0;
                s_off[buf * CEVT + lane]      = s0 - n0;
                s_off[buf * CEVT + lane + 32] = s1 - n1;
                unsigned T  = __shfl_sync(0xffffffffu, s1, 31);
                unsigned Tp = (T + 7u) & ~7u;
                if (Tp <= CAPC) {
                    if (lane < Tp - T) {     // identity pad: m=1, w=0
                        s_m[buf * CAPC + T + lane] = 1.0f;
                        s_j[buf * CAPC + T + lane] = (unsigned short)DH;
                    }
                    if (lane == 0) s_T[buf] = Tp;
                } else if (lane == 0) {
                    s_T[buf] = OVF;
                }
            }
            BAR_SYNC(3, 416);                // offsets + s_T visible

            // ---- compaction: each warp a strided set of events ----
            if (s_T[buf] != OVF) {
                for (int e0 = warp; e0 < CEVT; e0 += 13) {
                    unsigned m = (lane < 13) ? mk[e0 * 13 + lane] : 0u;
                    int c = __popc(m);
                    int sc = c;
                    #pragma unroll
                    for (int d = 1; d < 32; d <<= 1) {
                        int v = __shfl_up_sync(0xffffffffu, sc, d);
                        if (lane >= d) sc += v;
                    }
                    unsigned off = s_off[buf * CEVT + e0];
                    if (lane == 0) {         // decay entry
                        s_m[buf * CAPC + off] = s_d2[k * CEVT + e0];
                        s_j[buf * CAPC + off] = (unsigned short)DH;
                    }
                    unsigned pos = off + 1 + (unsigned)(sc - c);
                    while (m) {
                        int bit = __ffs(m) - 1;
                        m &= m - 1;
                        s_m[buf * CAPC + pos] = 1.0f;
                        s_j[buf * CAPC + pos] = (unsigned short)(lane * 32 + bit);
                        ++pos;
                    }
                }
            }
            BAR_ARRIVE(1, NT);               // chunk k ready for chain
        }
    } else {
        // =================== chain warp ===================
        // speculative-reset recurrence, 8 cyc/entry:
        //   t  = fma(u, m, w)          (u = pre-reset membrane)
        //   u' = f ? w : t             (f = fired flag of previous entry;
        //                               restart value fma(0,m,w) == w exactly)
        //   f' = (u' >= 0.5)
        float u2 = 0.0f, cnt = 0.0f;
        bool  f2 = false;
        for (int k = 0; k < NCH; ++k) {
            BAR_SYNC(1, NT);                 // chunk k ready
            const int buf = k & 1;
            const unsigned Tp = s_T[buf];
            if (lane < DOUT) {
                if (Tp != OVF) {
                    const float* mm = s_m + buf * CAPC;
                    const unsigned short* jj = s_j + buf * CAPC;
                    for (unsigned i = 0; i < Tp; i += 8) {
                        #pragma unroll
                        for (int u = 0; u < 8; ++u) {
                            float m = mm[i + u];
                            int   j = jj[i + u];
                            float w = s_W2p[j * DOUT + lane];
                            float t = __fmaf_rn(u2, m, w);
                            u2 = f2 ? w : t;
                            f2 = (u2 >= 0.5f);
                            cnt = f2 ? __fadd_rn(cnt, 1.0f) : cnt;
                        }
                    }
                } else {
                    // rare overflow: scan masks directly, ascending j
                    const unsigned* mk = s_mask + buf * CEVT * 13;
                    for (int e0 = 0; e0 < CEVT; ++e0) {
                        float d = s_d2[k * CEVT + e0];
                        float t = __fmaf_rn(u2, d, 0.0f);
                        u2 = f2 ? 0.0f : t;
                        f2 = (u2 >= 0.5f);
                        cnt = f2 ? __fadd_rn(cnt, 1.0f) : cnt;
                        for (int w = 0; w < 13; ++w) {
                            unsigned m = mk[e0 * 13 + w];
                            while (m) {
                                int bit = __ffs(m) - 1;
                                m &= m - 1;
                                int j = w * 32 + bit;
                                float wv = s_W2p[j * DOUT + lane];
                                float tt = __fmaf_rn(u2, 1.0f, wv);
                                u2 = f2 ? wv : tt;
                                f2 = (u2 >= 0.5f);
                                cnt = f2 ? __fadd_rn(cnt, 1.0f) : cnt;
                            }
                        }
                    }
                }
            }
            if (k < NCH - 2) BAR_ARRIVE(2, NT);   // free buffer for chunk k+2
        }
        if (lane < DOUT)
            out[b * DOUT + lane] = __fdiv_rn(cnt, 64.0f);
    }
}

extern "C" void kernel_launch(void* const* d_in, const int* in_sizes, int n_in,
                              void* d_out, int out_size) {
    const float* times = (const float*)d_in[0];  // [256,1024] f32
    const int*   pixv  = (const int*)d_in[1];    // [256,1024] i32
    const float* W1    = (const float*)d_in[2];  // [400,784]
    const float* b1    = (const float*)d_in[3];  // [400]
    const float* W2    = (const float*)d_in[4];  // [10,400]
    const float* b2    = (const float*)d_in[5];  // [10]

    static int attr_set = 0;
    if (!attr_set) {
        cudaFuncSetAttribute(snn_fused,
                             cudaFuncAttributeMaxDynamicSharedMemorySize,
                             SM_BYTES);
        attr_set = 1;
    }

    int prep_n = DIN * DH + (DH + 1) * DOUT;
    prep_kernel<<<(prep_n + 255) / 256, 256>>>(W1, W2, b2);
    snn_fused<<<BB, NT, SM_BYTES>>>(times, pixv, b1, (float*)d_out);
}